// round 1
// baseline (speedup 1.0000x reference)
#include <cuda_runtime.h>
#include <cuda_bf16.h>
#include <math.h>

// Problem constants (fixed by setup_inputs)
#define B_N 4096
#define M_N 256
#define D_N 256

#define TAU_INV_LOG2E 7.213475204444817f   // log2(e)/0.2
#define LAM_INV_LOG2E 0.18033688011112043f // log2(e)/8
#define TOPO_C 0.5f
#define LEN_C 0.01f
#define SP_C 0.001f

// ---------------- device scratch (no allocations allowed) ----------------
__device__ float g_dist[B_N * M_N];       // 4 MB
__device__ float g_factor[M_N];           // 1 + TOPO*degree[m]
__device__ float g_ep_rowsum[M_N];        // sum_j edge_prob[i][j]
__device__ float g_wl_rowsum[M_N];        // sum_j edge_prob[i][j]*protodist[i][j]
__device__ float g_part[B_N];             // per-row data_term partials

// ---------------- K0: edge probabilities, degree factor, proto distances ----------------
// grid = 256 blocks (one per prototype i), 256 threads (one per j)
__global__ void k_edges(const float* __restrict__ W, const float* __restrict__ E) {
    const int i = blockIdx.x;
    const int j = threadIdx.x;

    __shared__ float wi[D_N];
    __shared__ float red_ep[M_N];
    __shared__ float red_wl[M_N];

    wi[j] = W[i * D_N + j];
    __syncthreads();

    // symmetric edge prob, zero diagonal
    float lij = 0.5f * (E[i * M_N + j] + E[j * M_N + i]);
    float ep = __fdividef(1.0f, 1.0f + __expf(-lij));
    if (j == i) ep = 0.0f;

    // squared proto distance ||w_i - w_j||^2
    const float* wj = W + j * D_N;
    float pd = 0.0f;
#pragma unroll 8
    for (int k = 0; k < D_N; k++) {
        float d = wi[k] - wj[k];
        pd = fmaf(d, d, pd);
    }

    red_ep[j] = ep;
    red_wl[j] = ep * pd;
    __syncthreads();
    for (int s = 128; s > 0; s >>= 1) {
        if (j < s) {
            red_ep[j] += red_ep[j + s];
            red_wl[j] += red_wl[j + s];
        }
        __syncthreads();
    }
    if (j == 0) {
        float rsum = red_ep[0];
        g_ep_rowsum[i] = rsum;
        g_wl_rowsum[i] = red_wl[0];
        g_factor[i] = 1.0f + TOPO_C * (rsum / (float)(M_N - 1));
    }
}

// ---------------- K1: distances[b][m] = ||x_b - w_m|| ----------------
// Tiled: 64 b-rows x 64 m-cols per block, K chunks of 32; 256 threads, 4x4 microtile.
#define TB 64
#define TM 64
#define TK 32
#define LDT 68  // padded row stride (floats): 68*4B=272B, 16B-aligned rows, conflict-light

__global__ void k_dist(const float* __restrict__ X, const float* __restrict__ W) {
    __shared__ float As[TK][LDT]; // As[k][b]
    __shared__ float Bs[TK][LDT]; // Bs[k][m]

    const int t = threadIdx.x;
    const int tx = t & 15;        // m micro
    const int ty = t >> 4;        // b micro
    const int m0 = blockIdx.x * TM;
    const int b0 = blockIdx.y * TB;

    float acc[4][4];
#pragma unroll
    for (int i = 0; i < 4; i++)
#pragma unroll
        for (int j = 0; j < 4; j++) acc[i][j] = 0.0f;

    for (int k0 = 0; k0 < D_N; k0 += TK) {
#pragma unroll
        for (int p = 0; p < 8; p++) {
            int q = t + p * 256;   // 0..2047
            int r = q >> 5;        // row in tile (0..63)
            int c = q & 31;        // k in chunk
            As[c][r] = X[(b0 + r) * D_N + k0 + c];
            Bs[c][r] = W[(m0 + r) * D_N + k0 + c];
        }
        __syncthreads();

#pragma unroll
        for (int kk = 0; kk < TK; kk++) {
            float4 av = *(const float4*)&As[kk][ty * 4];
            float4 bv = *(const float4*)&Bs[kk][tx * 4];
            float a[4] = {av.x, av.y, av.z, av.w};
            float b[4] = {bv.x, bv.y, bv.z, bv.w};
#pragma unroll
            for (int i = 0; i < 4; i++)
#pragma unroll
                for (int j = 0; j < 4; j++) {
                    float d = a[i] - b[j];
                    acc[i][j] = fmaf(d, d, acc[i][j]);
                }
        }
        __syncthreads();
    }

#pragma unroll
    for (int i = 0; i < 4; i++) {
        int bb = b0 + ty * 4 + i;
#pragma unroll
        for (int j = 0; j < 4; j++) {
            int mm = m0 + tx * 4 + j;
            g_dist[bb * M_N + mm] = sqrtf(acc[i][j]);
        }
    }
}

// ---------------- K2: soft-rank + neighborhood + data-term partial per row ----------------
// grid = 4096 blocks (one per data point), 256 threads (one per prototype)
__global__ void k_rank() {
    const int b = blockIdx.x;
    const int t = threadIdx.x;

    __shared__ float u[M_N];
    __shared__ float red[M_N];
    __shared__ float fac_s[M_N];

    float d = g_dist[b * M_N + t];
    fac_s[t] = g_factor[t];

    // row max (for exp shift)
    red[t] = d;
    __syncthreads();
    for (int s = 128; s > 0; s >>= 1) {
        if (t < s) red[t] = fmaxf(red[t], red[t + s]);
        __syncthreads();
    }
    float dmax = red[0];
    __syncthreads();

    // u_j = exp((d_j - dmax)/tau), clamped to avoid 0/0 in far tails
    float arg = fmaxf((d - dmax) * TAU_INV_LOG2E, -100.0f);
    float ui = exp2f(arg);
    u[t] = ui;
    __syncthreads();

    // soft rank: sum_j sigmoid((d_i-d_j)/tau) = sum_j ui/(ui+uj); diagonal = 0.5
    float sum = 0.0f;
#pragma unroll 8
    for (int j = 0; j < M_N; j++) {
        sum += __fdividef(ui, ui + u[j]);
    }
    float srm1 = sum - 0.5f;              // soft_rank - 1
    float neigh = exp2f(-srm1 * LAM_INV_LOG2E);
    float contrib = neigh * d * fac_s[t];

    // deterministic block reduction
    red[t] = contrib;
    __syncthreads();
    for (int s = 128; s > 0; s >>= 1) {
        if (t < s) red[t] += red[t + s];
        __syncthreads();
    }
    if (t == 0) g_part[b] = red[0];
}

// ---------------- K3: final fixed-order reduction + loss assembly ----------------
__global__ void k_final(float* __restrict__ out) {
    const int t = threadIdx.x;
    __shared__ float red[256];

    // data term partials (4096, fixed-order strided then tree)
    float s = 0.0f;
    for (int i = t; i < B_N; i += 256) s += g_part[i];
    red[t] = s;
    __syncthreads();
    for (int k = 128; k > 0; k >>= 1) {
        if (t < k) red[t] += red[t + k];
        __syncthreads();
    }
    float data_sum = red[0];
    __syncthreads();

    // edge-prob sum
    red[t] = g_ep_rowsum[t];
    __syncthreads();
    for (int k = 128; k > 0; k >>= 1) {
        if (t < k) red[t] += red[t + k];
        __syncthreads();
    }
    float ep_sum = red[0];
    __syncthreads();

    // weighted length numerator
    red[t] = g_wl_rowsum[t];
    __syncthreads();
    for (int k = 128; k > 0; k >>= 1) {
        if (t < k) red[t] += red[t + k];
        __syncthreads();
    }
    float wl_sum = red[0];

    if (t == 0) {
        float data_term = data_sum / (float)(B_N * M_N);
        float weighted_len = wl_sum / (ep_sum + 1e-8f);
        float sparsity = ep_sum / (float)(M_N * M_N);
        out[0] = data_term + LEN_C * weighted_len + SP_C * sparsity;
    }
}

// ---------------- launch ----------------
extern "C" void kernel_launch(void* const* d_in, const int* in_sizes, int n_in,
                              void* d_out, int out_size) {
    const float* data = (const float*)d_in[0];     // [4096, 256]
    const float* weights = (const float*)d_in[1];  // [256, 256]
    const float* elog = (const float*)d_in[2];     // [256, 256]
    float* out = (float*)d_out;

    k_edges<<<M_N, M_N>>>(weights, elog);
    k_dist<<<dim3(M_N / TM, B_N / TB), 256>>>(data, weights);
    k_rank<<<B_N, M_N>>>();
    k_final<<<1, 256>>>(out);
}